// round 1
// baseline (speedup 1.0000x reference)
#include <cuda_runtime.h>
#include <math.h>

#define BB 16
#define SEQ 197
#define NROWS (BB*SEQ)        // 3152
#define DIMM 256
#define DI 512
#define DS 16
#define PD 768
#define NPATCH 196
#define PROWS (BB*NPATCH)     // 3136
#define NCLS 1000

// ---------------- scratch (device globals; no allocation allowed) -------------
__device__ float g_xp [PROWS*PD];       // patchified+LN1 rows
__device__ float g_xe [PROWS*DIMM];     // patch-embed GEMM out
__device__ float g_x  [NROWS*DIMM];     // current block output x
__device__ float g_res[NROWS*DIMM];     // residual
__device__ float g_xn [NROWS*DIMM];     // LN(residual)
__device__ float g_xz [NROWS*2*DI];     // in-proj out (xm | z)
__device__ float g_u  [NROWS*DI];       // conv+silu out
__device__ float g_dbc[NROWS*48];       // xproj out (dt16 | B16 | C16)
__device__ float g_dt [NROWS*DI];       // softplus dt
__device__ float g_y  [NROWS*DI];       // scan out (fused epilogue)
__device__ float g_cls[BB*DIMM];        // final LN of token 0

// ---------------- reduction helpers -------------------------------------------
__device__ __forceinline__ float blockReduce256(float v, float* red) {
    int lane = threadIdx.x & 31, w = threadIdx.x >> 5;
    #pragma unroll
    for (int o = 16; o; o >>= 1) v += __shfl_xor_sync(0xffffffffu, v, o);
    __syncthreads();
    if (lane == 0) red[w] = v;
    __syncthreads();
    float t = 0.f;
    if (w == 0) {
        t = (lane < 8) ? red[lane] : 0.f;
        #pragma unroll
        for (int o = 4; o; o >>= 1) t += __shfl_xor_sync(0xffffffffu, t, o);
        if (lane == 0) red[0] = t;
    }
    __syncthreads();
    float r = red[0];
    __syncthreads();
    return r;
}

__device__ __forceinline__ float siluf(float x) { return x / (1.f + expf(-x)); }

// ---------------- tiled SGEMM ---------------------------------------------------
// C[M,N] = A[M,K] @ B[K,N], row-major, 256 threads. (BM/TM)*(BN/TN)==256.
template<int BM, int BN, int BK, int TM, int TN>
__global__ void sgemm(const float* __restrict__ A, const float* __restrict__ B,
                      float* __restrict__ C, int M, int N, int K)
{
    __shared__ float As[BK][BM];
    __shared__ float Bs[BK][BN];
    const int tid = threadIdx.x;
    const int tx = tid % (BN / TN);
    const int ty = tid / (BN / TN);
    const int m0 = blockIdx.y * BM;
    const int n0 = blockIdx.x * BN;

    float acc[TM][TN];
    #pragma unroll
    for (int i = 0; i < TM; i++)
        #pragma unroll
        for (int j = 0; j < TN; j++) acc[i][j] = 0.f;

    for (int k0 = 0; k0 < K; k0 += BK) {
        #pragma unroll
        for (int idx = tid; idx < BM * BK; idx += 256) {
            int m = idx / BK, kk = idx % BK;
            int gm = m0 + m;
            As[kk][m] = (gm < M) ? A[(size_t)gm * K + k0 + kk] : 0.f;
        }
        #pragma unroll
        for (int idx = tid; idx < BK * BN; idx += 256) {
            int kk = idx / BN, n = idx % BN;
            int gn = n0 + n;
            Bs[kk][n] = (gn < N) ? B[(size_t)(k0 + kk) * N + gn] : 0.f;
        }
        __syncthreads();
        #pragma unroll
        for (int kk = 0; kk < BK; kk++) {
            float ra[TM], rb[TN];
            #pragma unroll
            for (int i = 0; i < TM; i++) ra[i] = As[kk][ty * TM + i];
            #pragma unroll
            for (int j = 0; j < TN; j++) rb[j] = Bs[kk][tx * TN + j];
            #pragma unroll
            for (int i = 0; i < TM; i++)
                #pragma unroll
                for (int j = 0; j < TN; j++) acc[i][j] += ra[i] * rb[j];
        }
        __syncthreads();
    }

    #pragma unroll
    for (int i = 0; i < TM; i++) {
        int gm = m0 + ty * TM + i;
        if (gm >= M) continue;
        #pragma unroll
        for (int j = 0; j < TN; j++) {
            int gn = n0 + tx * TN + j;
            if (gn < N) C[(size_t)gm * N + gn] = acc[i][j];
        }
    }
}

// ---------------- patchify + LN1 ----------------------------------------------
__global__ void patchify_ln(const float* __restrict__ img,
                            const float* __restrict__ gg, const float* __restrict__ bb)
{
    __shared__ float sv[PD];
    __shared__ float red[8];
    int r = blockIdx.x;                 // 0..3135
    int b = r / NPATCH, p = r % NPATCH;
    int hh = p / 14, ww = p % 14;
    int tid = threadIdx.x;              // 256
    float lsum = 0.f;
    #pragma unroll
    for (int e = tid; e < PD; e += 256) {
        int c = e % 3, t = e / 3, p2 = t % 16, p1 = t / 16;
        float v = img[(((size_t)(b * 3 + c) * 224 + hh * 16 + p1) * 224) + ww * 16 + p2];
        sv[e] = v; lsum += v;
    }
    float mu = blockReduce256(lsum, red) * (1.f / PD);
    float lq = 0.f;
    #pragma unroll
    for (int e = tid; e < PD; e += 256) { float d = sv[e] - mu; lq += d * d; }
    float var = blockReduce256(lq, red) * (1.f / PD);
    float rs = rsqrtf(var + 1e-5f);
    #pragma unroll
    for (int e = tid; e < PD; e += 256)
        g_xp[(size_t)r * PD + e] = (sv[e] - mu) * rs * gg[e] + bb[e];
}

// ---------------- bias + LN2 + pos_emb + cls token -----------------------------
__global__ void pe2_posemb(const float* __restrict__ pe_b,
                           const float* __restrict__ g2, const float* __restrict__ b2,
                           const float* __restrict__ pos, const float* __restrict__ cls)
{
    __shared__ float red[8];
    int blk = blockIdx.x;
    int c = threadIdx.x;                // 256
    if (blk < PROWS) {
        int b = blk / NPATCH, p = blk % NPATCH;
        float v = g_xe[(size_t)blk * DIMM + c] + pe_b[c];
        float mu = blockReduce256(v, red) * (1.f / DIMM);
        float d = v - mu;
        float var = blockReduce256(d * d, red) * (1.f / DIMM);
        float o = d * rsqrtf(var + 1e-5f) * g2[c] + b2[c];
        g_x[((size_t)(b * SEQ + 1 + p)) * DIMM + c] = o + pos[(1 + p) * DIMM + c];
    } else {
        int b = blk - PROWS;
        g_x[((size_t)(b * SEQ)) * DIMM + c] = cls[c] + pos[c];
    }
}

// ---------------- residual update + LN (warp per row) --------------------------
__global__ void ln_res(const float* __restrict__ lw, const float* __restrict__ lb, int init)
{
    int row = blockIdx.x * 8 + (threadIdx.x >> 5);
    int lane = threadIdx.x & 31;
    const float* xr = g_x + (size_t)row * DIMM;
    float* rr = g_res + (size_t)row * DIMM;
    float v[8]; float s = 0.f;
    #pragma unroll
    for (int j = 0; j < 8; j++) {
        int c = lane + j * 32;
        float t = xr[c];
        if (!init) t += rr[c];
        rr[c] = t; v[j] = t; s += t;
    }
    #pragma unroll
    for (int o = 16; o; o >>= 1) s += __shfl_xor_sync(0xffffffffu, s, o);
    float mu = s * (1.f / DIMM);
    float q = 0.f;
    #pragma unroll
    for (int j = 0; j < 8; j++) { float d = v[j] - mu; q += d * d; }
    #pragma unroll
    for (int o = 16; o; o >>= 1) q += __shfl_xor_sync(0xffffffffu, q, o);
    float rs = rsqrtf(q * (1.f / DIMM) + 1e-5f);
    #pragma unroll
    for (int j = 0; j < 8; j++) {
        int c = lane + j * 32;
        g_xn[(size_t)row * DIMM + c] = (v[j] - mu) * rs * lw[c] + lb[c];
    }
}

// ---------------- depthwise causal conv (k=4) + silu ---------------------------
__global__ void conv_silu(const float* __restrict__ cw, const float* __restrict__ cb)
{
    int i = blockIdx.x * 256 + threadIdx.x;
    if (i >= NROWS * DI) return;
    int d = i % DI; int row = i / DI; int l = row % SEQ; int b = row / SEQ;
    float acc = cb[d];
    const float* w = cw + d * 4;
    #pragma unroll
    for (int k = 0; k < 4; k++) {
        int ll = l - 3 + k;
        if (ll >= 0) acc += g_xz[((size_t)(b * SEQ + ll)) * (2 * DI) + d] * w[k];
    }
    g_u[(size_t)row * DI + d] = siluf(acc);
}

// ---------------- u @ xproj_w -> dbc[rows,48] ----------------------------------
__global__ void xproj_k(const float* __restrict__ w)
{
    int i = blockIdx.x * 256 + threadIdx.x;
    if (i >= NROWS * 48) return;
    int c = i % 48; int row = i / 48;
    const float* ur = g_u + (size_t)row * DI;
    float acc = 0.f;
    #pragma unroll 4
    for (int k = 0; k < DI; k++) acc += ur[k] * w[k * 48 + c];
    g_dbc[i] = acc;
}

// ---------------- dt = softplus(dbc[:,:16] @ dtw + dtb) ------------------------
__global__ void dtproj_k(const float* __restrict__ w, const float* __restrict__ bias)
{
    int i = blockIdx.x * 256 + threadIdx.x;
    if (i >= NROWS * DI) return;
    int d = i % DI; int row = i / DI;
    float acc = bias[d];
    const float* dr = g_dbc + (size_t)row * 48;
    #pragma unroll
    for (int k = 0; k < 16; k++) acc += dr[k] * w[k * DI + d];
    g_dt[i] = (acc > 20.f) ? acc : log1pf(expf(acc));
}

// ---------------- selective scan + fused epilogue ------------------------------
// grid: 16 b * 8 chunks; block 128 threads; 2 threads per channel (8 states each).
__global__ void scan_k(const float* __restrict__ A_log, const float* __restrict__ Dpv)
{
    __shared__ float sBC[2][32];
    int b = blockIdx.x >> 3;
    int chunk = blockIdx.x & 7;
    int tid = threadIdx.x;
    int d = chunk * 64 + (tid >> 1);
    int half = tid & 1;
    int n0 = half * 8;

    float A2[8], hst[8];
    #pragma unroll
    for (int j = 0; j < 8; j++) {
        A2[j] = -expf(A_log[(size_t)d * DS + n0 + j]) * 1.4426950408889634f;
        hst[j] = 0.f;
    }
    float dpd = Dpv[d];

    for (int l = 0; l < SEQ; l++) {
        int row = b * SEQ + l;
        int buf = l & 1;
        if (tid < 32) sBC[buf][tid] = g_dbc[(size_t)row * 48 + 16 + tid];
        float dt_t = g_dt[(size_t)row * DI + d];
        float u_t  = g_u [(size_t)row * DI + d];
        __syncthreads();
        float xt = dt_t * u_t;
        float y = 0.f;
        #pragma unroll
        for (int j = 0; j < 8; j++) {
            float dA = exp2f(dt_t * A2[j]);
            float hv = dA * hst[j] + xt * sBC[buf][n0 + j];
            hst[j] = hv;
            y += hv * sBC[buf][16 + n0 + j];
        }
        y += __shfl_xor_sync(0xffffffffu, y, 1);
        if (!half) {
            float z = g_xz[(size_t)row * (2 * DI) + DI + d];
            g_y[(size_t)row * DI + d] = (y + u_t * dpd) * siluf(z);
        }
    }
}

// ---------------- final LN on token 0 ------------------------------------------
__global__ void ln_cls_k(const float* __restrict__ gw, const float* __restrict__ gb)
{
    __shared__ float red[8];
    int b = blockIdx.x; int c = threadIdx.x;
    size_t idx = (size_t)(b * SEQ) * DIMM + c;
    float v = g_x[idx] + g_res[idx];
    float mu = blockReduce256(v, red) * (1.f / DIMM);
    float d = v - mu;
    float var = blockReduce256(d * d, red) * (1.f / DIMM);
    g_cls[b * DIMM + c] = d * rsqrtf(var + 1e-5f) * gw[c] + gb[c];
}

// ---------------- head ----------------------------------------------------------
__global__ void head_k(const float* __restrict__ hw, const float* __restrict__ hb,
                       float* __restrict__ out)
{
    int i = blockIdx.x * 256 + threadIdx.x;
    if (i >= BB * NCLS) return;
    int n = i % NCLS, b = i / NCLS;
    const float* xr = g_cls + b * DIMM;
    float acc = hb[n];
    #pragma unroll 4
    for (int k = 0; k < DIMM; k++) acc += xr[k] * hw[k * NCLS + n];
    out[i] = acc;
}

// ---------------- launch ---------------------------------------------------------
extern "C" void kernel_launch(void* const* d_in, const int* in_sizes, int n_in,
                              void* d_out, int out_size)
{
    (void)in_sizes; (void)n_in; (void)out_size;
    const float* img      = (const float*)d_in[0];
    const float* pe_ln1_g = (const float*)d_in[1];
    const float* pe_ln1_b = (const float*)d_in[2];
    const float* pe_w     = (const float*)d_in[3];
    const float* pe_b     = (const float*)d_in[4];
    const float* pe_ln2_g = (const float*)d_in[5];
    const float* pe_ln2_b = (const float*)d_in[6];
    const float* pos_emb  = (const float*)d_in[7];
    const float* cls_tok  = (const float*)d_in[8];
    const float* ln_w     = (const float*)d_in[9];
    const float* ln_b     = (const float*)d_in[10];
    const float* in_w     = (const float*)d_in[11];
    const float* conv_w   = (const float*)d_in[12];
    const float* conv_b   = (const float*)d_in[13];
    const float* xproj_w  = (const float*)d_in[14];
    const float* dtproj_w = (const float*)d_in[15];
    const float* dtproj_b = (const float*)d_in[16];
    const float* A_log    = (const float*)d_in[17];
    const float* Dp       = (const float*)d_in[18];
    const float* out_w    = (const float*)d_in[19];
    const float* normf_w  = (const float*)d_in[20];
    const float* normf_b  = (const float*)d_in[21];
    const float* head_w   = (const float*)d_in[22];
    const float* head_b   = (const float*)d_in[23];
    float* out = (float*)d_out;

    float *p_xp, *p_xe, *p_xn, *p_xz, *p_y, *p_x;
    cudaGetSymbolAddress((void**)&p_xp, g_xp);
    cudaGetSymbolAddress((void**)&p_xe, g_xe);
    cudaGetSymbolAddress((void**)&p_xn, g_xn);
    cudaGetSymbolAddress((void**)&p_xz, g_xz);
    cudaGetSymbolAddress((void**)&p_y , g_y );
    cudaGetSymbolAddress((void**)&p_x , g_x );

    // patch embed
    patchify_ln<<<PROWS, 256>>>(img, pe_ln1_g, pe_ln1_b);
    {   // g_xe = g_xp @ pe_w   (3136 x 768 x 256)
        dim3 grid(DIMM / 64, (PROWS + 63) / 64);
        sgemm<64, 64, 8, 4, 4><<<grid, 256>>>(p_xp, pe_w, p_xe, PROWS, DIMM, PD);
    }
    pe2_posemb<<<PROWS + BB, 256>>>(pe_b, pe_ln2_g, pe_ln2_b, pos_emb, cls_tok);

    for (int i = 0; i < 8; i++) {
        ln_res<<<NROWS / 8, 256>>>(ln_w + i * DIMM, ln_b + i * DIMM, (i == 0) ? 1 : 0);
        {   // g_xz = g_xn @ in_w[i]  (3152 x 256 x 1024)
            dim3 grid((2 * DI) / 128, (NROWS + 127) / 128);
            sgemm<128, 128, 8, 8, 8><<<grid, 256>>>(p_xn, in_w + (size_t)i * DIMM * 2 * DI,
                                                    p_xz, NROWS, 2 * DI, DIMM);
        }
        conv_silu<<<(NROWS * DI) / 256, 256>>>(conv_w + (size_t)i * DI * 4, conv_b + i * DI);
        xproj_k<<<(NROWS * 48) / 256, 256>>>(xproj_w + (size_t)i * DI * 48);
        dtproj_k<<<(NROWS * DI) / 256, 256>>>(dtproj_w + (size_t)i * 16 * DI, dtproj_b + i * DI);
        scan_k<<<BB * 8, 128>>>(A_log + (size_t)i * DI * DS, Dp + i * DI);
        {   // g_x = g_y @ out_w[i]  (3152 x 512 x 256)
            dim3 grid(DIMM / 64, (NROWS + 63) / 64);
            sgemm<64, 64, 8, 4, 4><<<grid, 256>>>(p_y, out_w + (size_t)i * DI * DIMM,
                                                  p_x, NROWS, DIMM, DI);
        }
    }

    ln_cls_k<<<BB, 256>>>(normf_w, normf_b);
    head_k<<<(BB * NCLS + 255) / 256, 256>>>(head_w, head_b, out);
}

// round 2
// speedup vs baseline: 1.6081x; 1.6081x over previous
#include <cuda_runtime.h>
#include <math.h>
#include <stdint.h>

#define BB 16
#define SEQ 197
#define NROWS (BB*SEQ)        // 3152
#define DIMM 256
#define DI 512
#define DS 16
#define PD 768
#define NPATCH 196
#define PROWS (BB*NPATCH)     // 3136
#define NCLS 1000

// ---------------- scratch (device globals; no allocation allowed) -------------
__device__ float g_xp [PROWS*PD];
__device__ float g_xe [PROWS*DIMM];
__device__ float g_x  [NROWS*DIMM];
__device__ float g_res[NROWS*DIMM];
__device__ float g_xn [NROWS*DIMM];
__device__ float g_xz [NROWS*2*DI];
__device__ float g_u  [NROWS*DI];
__device__ float g_dbc[NROWS*48];
__device__ float g_dt [NROWS*DI];
__device__ float g_y  [NROWS*DI];
__device__ float g_cls[BB*DIMM];

// ---------------- fast math helpers -------------------------------------------
__device__ __forceinline__ float fex2(float x){ float y; asm("ex2.approx.ftz.f32 %0,%1;":"=f"(y):"f"(x)); return y; }
__device__ __forceinline__ float flg2(float x){ float y; asm("lg2.approx.ftz.f32 %0,%1;":"=f"(y):"f"(x)); return y; }
__device__ __forceinline__ float frcp(float x){ float y; asm("rcp.approx.ftz.f32 %0,%1;":"=f"(y):"f"(x)); return y; }
#define LOG2E 1.4426950408889634f
#define LN2   0.6931471805599453f
__device__ __forceinline__ float siluf(float x){ return x * frcp(1.f + fex2(-x * LOG2E)); }
__device__ __forceinline__ float softplusf(float x){
    return (x > 20.f) ? x : LN2 * flg2(1.f + fex2(x * LOG2E));
}
__device__ __forceinline__ uint32_t f2tf32(float f){
    uint32_t u; asm("cvt.rna.tf32.f32 %0, %1;" : "=r"(u) : "f"(f)); return u;
}

__device__ __forceinline__ float blockReduce256(float v, float* red) {
    int lane = threadIdx.x & 31, w = threadIdx.x >> 5;
    #pragma unroll
    for (int o = 16; o; o >>= 1) v += __shfl_xor_sync(0xffffffffu, v, o);
    __syncthreads();
    if (lane == 0) red[w] = v;
    __syncthreads();
    float t = 0.f;
    if (w == 0) {
        t = (lane < 8) ? red[lane] : 0.f;
        #pragma unroll
        for (int o = 4; o; o >>= 1) t += __shfl_xor_sync(0xffffffffu, t, o);
        if (lane == 0) red[0] = t;
    }
    __syncthreads();
    float r = red[0];
    __syncthreads();
    return r;
}

// ---------------- tf32 tensor-core GEMM ---------------------------------------
// C[M,N] = A[M,K] @ B[K,N], row-major fp32 in/out, tf32 mma, fp32 accum.
// BK=32 fixed, double-buffered smem, XOR swizzle for conflict-free LDS.
__device__ __forceinline__ void mma_tf32(float c[4], uint32_t a0, uint32_t a1, uint32_t a2, uint32_t a3,
                                         uint32_t b0, uint32_t b1) {
    asm volatile(
        "mma.sync.aligned.m16n8k8.row.col.f32.tf32.tf32.f32 "
        "{%0,%1,%2,%3},{%4,%5,%6,%7},{%8,%9},{%0,%1,%2,%3};\n"
        : "+f"(c[0]), "+f"(c[1]), "+f"(c[2]), "+f"(c[3])
        : "r"(a0), "r"(a1), "r"(a2), "r"(a3), "r"(b0), "r"(b1));
}

template<int BM, int BN, int WM, int WN>
__global__ void __launch_bounds__((BM/WM)*(BN/WN)*32)
mmatf32(const float* __restrict__ A, const float* __restrict__ B,
        float* __restrict__ C, int M, int N, int K)
{
    constexpr int BK = 32;
    constexpr int WARPS_M = BM / WM, WARPS_N = BN / WN;
    constexpr int NTHR = WARPS_M * WARPS_N * 32;
    constexpr int MI = WM / 16, NI = WN / 8;
    constexpr int A_C4 = NTHR / BM;        // float4 k-columns covered per pass
    constexpr int A_IT = BM * (BK/4) / NTHR;
    constexpr int B_R  = NTHR / (BN / 4);  // k rows covered per pass
    constexpr int B_IT = (BK) * (BN/4) / NTHR;

    extern __shared__ float sm[];
    float* As = sm;                 // [2][BK*BM]
    float* Bs = sm + 2 * BK * BM;   // [2][BK*BN]

    const int tid = threadIdx.x;
    const int lane = tid & 31, warp = tid >> 5;
    const int g = lane >> 2, tin = lane & 3;
    const int wm = warp % WARPS_M, wn = warp / WARPS_M;
    const int m_base = wm * WM, n_base = wn * WN;
    const int m0 = blockIdx.y * BM, n0 = blockIdx.x * BN;

    // staging coords
    const int mA = tid % BM, c4A = tid / BM;
    const int n4B = tid % (BN / 4), kB = tid / (BN / 4);
    const int gmA = m0 + mA;
    const bool aval = (gmA < M);

    float acc[MI][NI][4];
    #pragma unroll
    for (int i = 0; i < MI; i++)
        #pragma unroll
        for (int j = 0; j < NI; j++)
            #pragma unroll
            for (int t = 0; t < 4; t++) acc[i][j][t] = 0.f;

    float4 av[A_IT], bv[B_IT];

    auto ldgA = [&](int k0) {
        #pragma unroll
        for (int i = 0; i < A_IT; i++) {
            int k4 = c4A + i * A_C4;
            av[i] = aval ? *(const float4*)(A + (size_t)gmA * K + k0 + k4 * 4)
                         : make_float4(0.f,0.f,0.f,0.f);
        }
    };
    auto ldgB = [&](int k0) {
        #pragma unroll
        for (int i = 0; i < B_IT; i++) {
            int k = kB + i * B_R;
            int gn = n0 + n4B * 4;
            const float* br = B + (size_t)(k0 + k) * N;
            float4 v;
            if (gn + 3 < N) v = *(const float4*)(br + gn);
            else {
                v.x = (gn   < N) ? br[gn]   : 0.f;
                v.y = (gn+1 < N) ? br[gn+1] : 0.f;
                v.z = (gn+2 < N) ? br[gn+2] : 0.f;
                v.w = (gn+3 < N) ? br[gn+3] : 0.f;
            }
            bv[i] = v;
        }
    };
    auto stsA = [&](int buf) {
        float* dst = As + buf * BK * BM;
        #pragma unroll
        for (int i = 0; i < A_IT; i++) {
            int k4 = c4A + i * A_C4;
            float vv[4] = {av[i].x, av[i].y, av[i].z, av[i].w};
            #pragma unroll
            for (int j = 0; j < 4; j++) {
                int k = k4 * 4 + j;
                dst[k * BM + (mA ^ ((k & 3) * 8))] = __uint_as_float(f2tf32(vv[j]));
            }
        }
    };
    auto stsB = [&](int buf) {
        float* dst = Bs + buf * BK * BN;
        #pragma unroll
        for (int i = 0; i < B_IT; i++) {
            int k = kB + i * B_R;
            int n = n4B * 4;
            float4 v = bv[i];
            v.x = __uint_as_float(f2tf32(v.x));
            v.y = __uint_as_float(f2tf32(v.y));
            v.z = __uint_as_float(f2tf32(v.z));
            v.w = __uint_as_float(f2tf32(v.w));
            *(float4*)(dst + k * BN + (n ^ ((k & 3) * 8))) = v;
        }
    };
    auto compute = [&](int buf) {
        const float* as = As + buf * BK * BM;
        const float* bs = Bs + buf * BK * BN;
        const int s = tin * 8;
        #pragma unroll
        for (int ks = 0; ks < 4; ks++) {
            int ka = ks * 8 + tin;
            uint32_t af[MI][4], bf[NI][2];
            #pragma unroll
            for (int mi = 0; mi < MI; mi++) {
                int r0 = m_base + mi * 16 + g;
                af[mi][0] = __float_as_uint(as[ka * BM + (r0 ^ s)]);
                af[mi][1] = __float_as_uint(as[ka * BM + ((r0 + 8) ^ s)]);
                af[mi][2] = __float_as_uint(as[(ka + 4) * BM + (r0 ^ s)]);
                af[mi][3] = __float_as_uint(as[(ka + 4) * BM + ((r0 + 8) ^ s)]);
            }
            #pragma unroll
            for (int ni = 0; ni < NI; ni++) {
                int c0 = n_base + ni * 8 + g;
                bf[ni][0] = __float_as_uint(bs[ka * BN + (c0 ^ s)]);
                bf[ni][1] = __float_as_uint(bs[(ka + 4) * BN + (c0 ^ s)]);
            }
            #pragma unroll
            for (int mi = 0; mi < MI; mi++)
                #pragma unroll
                for (int ni = 0; ni < NI; ni++)
                    mma_tf32(acc[mi][ni], af[mi][0], af[mi][1], af[mi][2], af[mi][3],
                             bf[ni][0], bf[ni][1]);
        }
    };

    int nchunk = K / BK;
    ldgA(0); ldgB(0);
    stsA(0); stsB(0);
    __syncthreads();
    int buf = 0;
    for (int kc = 1; kc < nchunk; kc++) {
        ldgA(kc * BK); ldgB(kc * BK);
        compute(buf);
        stsA(buf ^ 1); stsB(buf ^ 1);
        __syncthreads();
        buf ^= 1;
    }
    compute(buf);

    // epilogue
    #pragma unroll
    for (int mi = 0; mi < MI; mi++) {
        int gr0 = m0 + m_base + mi * 16 + g;
        int gr1 = gr0 + 8;
        #pragma unroll
        for (int ni = 0; ni < NI; ni++) {
            int gc = n0 + n_base + ni * 8 + tin * 2;
            if (gc < N) {
                if (gr0 < M) *(float2*)(C + (size_t)gr0 * N + gc) = make_float2(acc[mi][ni][0], acc[mi][ni][1]);
                if (gr1 < M) *(float2*)(C + (size_t)gr1 * N + gc) = make_float2(acc[mi][ni][2], acc[mi][ni][3]);
            }
        }
    }
}

// ---------------- patchify + LN1 ----------------------------------------------
__global__ void patchify_ln(const float* __restrict__ img,
                            const float* __restrict__ gg, const float* __restrict__ bb)
{
    __shared__ float sv[PD];
    __shared__ float red[8];
    int r = blockIdx.x;
    int b = r / NPATCH, p = r % NPATCH;
    int hh = p / 14, ww = p % 14;
    int tid = threadIdx.x;
    float lsum = 0.f;
    #pragma unroll
    for (int e = tid; e < PD; e += 256) {
        int c = e % 3, t = e / 3, p2 = t % 16, p1 = t / 16;
        float v = img[(((size_t)(b * 3 + c) * 224 + hh * 16 + p1) * 224) + ww * 16 + p2];
        sv[e] = v; lsum += v;
    }
    float mu = blockReduce256(lsum, red) * (1.f / PD);
    float lq = 0.f;
    #pragma unroll
    for (int e = tid; e < PD; e += 256) { float d = sv[e] - mu; lq += d * d; }
    float var = blockReduce256(lq, red) * (1.f / PD);
    float rs = rsqrtf(var + 1e-5f);
    #pragma unroll
    for (int e = tid; e < PD; e += 256)
        g_xp[(size_t)r * PD + e] = (sv[e] - mu) * rs * gg[e] + bb[e];
}

// ---------------- bias + LN2 + pos_emb + cls token -----------------------------
__global__ void pe2_posemb(const float* __restrict__ pe_b,
                           const float* __restrict__ g2, const float* __restrict__ b2,
                           const float* __restrict__ pos, const float* __restrict__ cls)
{
    __shared__ float red[8];
    int blk = blockIdx.x;
    int c = threadIdx.x;
    if (blk < PROWS) {
        int b = blk / NPATCH, p = blk % NPATCH;
        float v = g_xe[(size_t)blk * DIMM + c] + pe_b[c];
        float mu = blockReduce256(v, red) * (1.f / DIMM);
        float d = v - mu;
        float var = blockReduce256(d * d, red) * (1.f / DIMM);
        float o = d * rsqrtf(var + 1e-5f) * g2[c] + b2[c];
        g_x[((size_t)(b * SEQ + 1 + p)) * DIMM + c] = o + pos[(1 + p) * DIMM + c];
    } else {
        int b = blk - PROWS;
        g_x[((size_t)(b * SEQ)) * DIMM + c] = cls[c] + pos[c];
    }
}

// ---------------- residual update + LN (warp per row) --------------------------
__global__ void ln_res(const float* __restrict__ lw, const float* __restrict__ lb, int init)
{
    int row = blockIdx.x * 8 + (threadIdx.x >> 5);
    int lane = threadIdx.x & 31;
    const float* xr = g_x + (size_t)row * DIMM;
    float* rr = g_res + (size_t)row * DIMM;
    float v[8]; float s = 0.f;
    #pragma unroll
    for (int j = 0; j < 8; j++) {
        int c = lane + j * 32;
        float t = xr[c];
        if (!init) t += rr[c];
        rr[c] = t; v[j] = t; s += t;
    }
    #pragma unroll
    for (int o = 16; o; o >>= 1) s += __shfl_xor_sync(0xffffffffu, s, o);
    float mu = s * (1.f / DIMM);
    float q = 0.f;
    #pragma unroll
    for (int j = 0; j < 8; j++) { float d = v[j] - mu; q += d * d; }
    #pragma unroll
    for (int o = 16; o; o >>= 1) q += __shfl_xor_sync(0xffffffffu, q, o);
    float rs = rsqrtf(q * (1.f / DIMM) + 1e-5f);
    #pragma unroll
    for (int j = 0; j < 8; j++) {
        int c = lane + j * 32;
        g_xn[(size_t)row * DIMM + c] = (v[j] - mu) * rs * lw[c] + lb[c];
    }
}

// ---------------- depthwise causal conv (k=4) + silu ---------------------------
__global__ void conv_silu(const float* __restrict__ cw, const float* __restrict__ cb)
{
    int i = blockIdx.x * 256 + threadIdx.x;
    if (i >= NROWS * DI) return;
    int d = i % DI; int row = i / DI; int l = row % SEQ; int b = row / SEQ;
    float acc = cb[d];
    const float* w = cw + d * 4;
    #pragma unroll
    for (int k = 0; k < 4; k++) {
        int ll = l - 3 + k;
        if (ll >= 0) acc += g_xz[((size_t)(b * SEQ + ll)) * (2 * DI) + d] * w[k];
    }
    g_u[(size_t)row * DI + d] = siluf(acc);
}

// ---------------- dt = softplus(dbc[:,:16] @ dtw + dtb) ------------------------
__global__ void dtproj_k(const float* __restrict__ w, const float* __restrict__ bias)
{
    int i = blockIdx.x * 256 + threadIdx.x;
    if (i >= NROWS * DI) return;
    int d = i % DI; int row = i / DI;
    float acc = bias[d];
    const float* dr = g_dbc + (size_t)row * 48;
    #pragma unroll
    for (int k = 0; k < 16; k++) acc += dr[k] * w[k * DI + d];
    g_dt[i] = softplusf(acc);
}

// ---------------- selective scan + fused epilogue (software pipelined) ----------
__global__ void scan_k(const float* __restrict__ A_log, const float* __restrict__ Dpv)
{
    __shared__ float sBC[2][32];
    int b = blockIdx.x >> 3;
    int chunk = blockIdx.x & 7;
    int tid = threadIdx.x;
    int d = chunk * 64 + (tid >> 1);
    int half = tid & 1;
    int n0 = half * 8;

    float A2[8], hst[8];
    #pragma unroll
    for (int j = 0; j < 8; j++) {
        A2[j] = -expf(A_log[(size_t)d * DS + n0 + j]) * LOG2E;
        hst[j] = 0.f;
    }
    float dpd = Dpv[d];

    int row0 = b * SEQ;
    if (tid < 32) sBC[0][tid] = g_dbc[(size_t)row0 * 48 + 16 + tid];
    float dt = g_dt[(size_t)row0 * DI + d];
    float u  = g_u [(size_t)row0 * DI + d];
    __syncthreads();

    for (int l = 0; l < SEQ; l++) {
        int row = row0 + l;
        int buf = l & 1;
        float dtn = 0.f, un = 0.f;
        if (l + 1 < SEQ) {
            if (tid < 32) sBC[buf ^ 1][tid] = g_dbc[(size_t)(row + 1) * 48 + 16 + tid];
            dtn = g_dt[(size_t)(row + 1) * DI + d];
            un  = g_u [(size_t)(row + 1) * DI + d];
        }
        float xt = dt * u;
        float y = 0.f;
        #pragma unroll
        for (int j = 0; j < 8; j++) {
            float dA = fex2(dt * A2[j]);
            float hv = dA * hst[j] + xt * sBC[buf][n0 + j];
            hst[j] = hv;
            y += hv * sBC[buf][16 + n0 + j];
        }
        y += __shfl_xor_sync(0xffffffffu, y, 1);
        if (!half) {
            float z = g_xz[(size_t)row * (2 * DI) + DI + d];
            g_y[(size_t)row * DI + d] = (y + u * dpd) * siluf(z);
        }
        dt = dtn; u = un;
        __syncthreads();
    }
}

// ---------------- final LN on token 0 ------------------------------------------
__global__ void ln_cls_k(const float* __restrict__ gw, const float* __restrict__ gb)
{
    __shared__ float red[8];
    int b = blockIdx.x; int c = threadIdx.x;
    size_t idx = (size_t)(b * SEQ) * DIMM + c;
    float v = g_x[idx] + g_res[idx];
    float mu = blockReduce256(v, red) * (1.f / DIMM);
    float d = v - mu;
    float var = blockReduce256(d * d, red) * (1.f / DIMM);
    g_cls[b * DIMM + c] = d * rsqrtf(var + 1e-5f) * gw[c] + gb[c];
}

// ---------------- head ----------------------------------------------------------
__global__ void head_k(const float* __restrict__ hw, const float* __restrict__ hb,
                       float* __restrict__ out)
{
    int i = blockIdx.x * 256 + threadIdx.x;
    if (i >= BB * NCLS) return;
    int n = i % NCLS, b = i / NCLS;
    const float* xr = g_cls + b * DIMM;
    float acc = hb[n];
    #pragma unroll 4
    for (int k = 0; k < DIMM; k++) acc += xr[k] * hw[k * NCLS + n];
    out[i] = acc;
}

// ---------------- launch ---------------------------------------------------------
extern "C" void kernel_launch(void* const* d_in, const int* in_sizes, int n_in,
                              void* d_out, int out_size)
{
    (void)in_sizes; (void)n_in; (void)out_size;
    const float* img      = (const float*)d_in[0];
    const float* pe_ln1_g = (const float*)d_in[1];
    const float* pe_ln1_b = (const float*)d_in[2];
    const float* pe_w     = (const float*)d_in[3];
    const float* pe_b     = (const float*)d_in[4];
    const float* pe_ln2_g = (const float*)d_in[5];
    const float* pe_ln2_b = (const float*)d_in[6];
    const float* pos_emb  = (const float*)d_in[7];
    const float* cls_tok  = (const float*)d_in[8];
    const float* ln_w     = (const float*)d_in[9];
    const float* ln_b     = (const float*)d_in[10];
    const float* in_w     = (const float*)d_in[11];
    const float* conv_w   = (const float*)d_in[12];
    const float* conv_b   = (const float*)d_in[13];
    const float* xproj_w  = (const float*)d_in[14];
    const float* dtproj_w = (const float*)d_in[15];
    const float* dtproj_b = (const float*)d_in[16];
    const float* A_log    = (const float*)d_in[17];
    const float* Dp       = (const float*)d_in[18];
    const float* out_w    = (const float*)d_in[19];
    const float* normf_w  = (const float*)d_in[20];
    const float* normf_b  = (const float*)d_in[21];
    const float* head_w   = (const float*)d_in[22];
    const float* head_b   = (const float*)d_in[23];
    float* out = (float*)d_out;

    float *p_xp, *p_xe, *p_xn, *p_xz, *p_y, *p_x, *p_u, *p_dbc;
    cudaGetSymbolAddress((void**)&p_xp, g_xp);
    cudaGetSymbolAddress((void**)&p_xe, g_xe);
    cudaGetSymbolAddress((void**)&p_xn, g_xn);
    cudaGetSymbolAddress((void**)&p_xz, g_xz);
    cudaGetSymbolAddress((void**)&p_y , g_y );
    cudaGetSymbolAddress((void**)&p_x , g_x );
    cudaGetSymbolAddress((void**)&p_u , g_u );
    cudaGetSymbolAddress((void**)&p_dbc, g_dbc);

    const int SMEM1 = 2 * 32 * (128 + 128) * 4;   // 65536
    const int SMEM2 = 2 * 32 * (64 + 64) * 4;     // 32768
    cudaFuncSetAttribute((const void*)mmatf32<128,128,64,32>,
                         cudaFuncAttributeMaxDynamicSharedMemorySize, SMEM1);
    cudaFuncSetAttribute((const void*)mmatf32<64,64,32,32>,
                         cudaFuncAttributeMaxDynamicSharedMemorySize, SMEM2);

    // patch embed
    patchify_ln<<<PROWS, 256>>>(img, pe_ln1_g, pe_ln1_b);
    {   // g_xe = g_xp @ pe_w   (3136 x 256 x 768)
        dim3 grid(DIMM / 64, PROWS / 64);
        mmatf32<64,64,32,32><<<grid, 128, SMEM2>>>(p_xp, pe_w, p_xe, PROWS, DIMM, PD);
    }
    pe2_posemb<<<PROWS + BB, 256>>>(pe_b, pe_ln2_g, pe_ln2_b, pos_emb, cls_tok);

    for (int i = 0; i < 8; i++) {
        ln_res<<<NROWS / 8, 256>>>(ln_w + i * DIMM, ln_b + i * DIMM, (i == 0) ? 1 : 0);
        {   // g_xz = g_xn @ in_w[i]  (3152 x 1024 x 256)
            dim3 grid((2 * DI) / 128, (NROWS + 127) / 128);
            mmatf32<128,128,64,32><<<grid, 256, SMEM1>>>(p_xn, in_w + (size_t)i * DIMM * 2 * DI,
                                                         p_xz, NROWS, 2 * DI, DIMM);
        }
        conv_silu<<<(NROWS * DI) / 256, 256>>>(conv_w + (size_t)i * DI * 4, conv_b + i * DI);
        {   // g_dbc = g_u @ xproj_w[i]  (3152 x 48 x 512)
            dim3 grid(1, (NROWS + 63) / 64);
            mmatf32<64,64,32,32><<<grid, 128, SMEM2>>>(p_u, xproj_w + (size_t)i * DI * 48,
                                                       p_dbc, NROWS, 48, DI);
        }
        dtproj_k<<<(NROWS * DI) / 256, 256>>>(dtproj_w + (size_t)i * 16 * DI, dtproj_b + i * DI);
        scan_k<<<BB * 8, 128>>>(A_log + (size_t)i * DI * DS, Dp + i * DI);
        {   // g_x = g_y @ out_w[i]  (3152 x 256 x 512)
            dim3 grid(DIMM / 64, (NROWS + 63) / 64);
            mmatf32<64,64,32,32><<<grid, 128, SMEM2>>>(p_y, out_w + (size_t)i * DI * DIMM,
                                                       p_x, NROWS, DIMM, DI);
        }
    }

    ln_cls_k<<<BB, 256>>>(normf_w, normf_b);
    head_k<<<(BB * NCLS + 255) / 256, 256>>>(head_w, head_b, out);
}

// round 3
// speedup vs baseline: 2.0932x; 1.3017x over previous
#include <cuda_runtime.h>
#include <math.h>
#include <stdint.h>

#define BB 16
#define SEQ 197
#define NROWS (BB*SEQ)        // 3152
#define DIMM 256
#define DI 512
#define DS 16
#define PD 768
#define NPATCH 196
#define PROWS (BB*NPATCH)     // 3136
#define NCLS 1000

// ---------------- scratch (device globals; no allocation allowed) -------------
__device__ float g_xp [PROWS*PD];
__device__ float g_xe [PROWS*DIMM];
__device__ float g_x  [NROWS*DIMM];
__device__ float g_res[NROWS*DIMM];
__device__ float g_xn [NROWS*DIMM];
__device__ float g_xz [NROWS*2*DI];
__device__ float g_u  [NROWS*DI];
__device__ float g_dbc[NROWS*48];
__device__ float g_y  [NROWS*DI];
__device__ float g_cls[BB*DIMM];

// ---------------- fast math helpers -------------------------------------------
__device__ __forceinline__ float fex2(float x){ float y; asm("ex2.approx.ftz.f32 %0,%1;":"=f"(y):"f"(x)); return y; }
__device__ __forceinline__ float flg2(float x){ float y; asm("lg2.approx.ftz.f32 %0,%1;":"=f"(y):"f"(x)); return y; }
__device__ __forceinline__ float frcp(float x){ float y; asm("rcp.approx.ftz.f32 %0,%1;":"=f"(y):"f"(x)); return y; }
#define LOG2E 1.4426950408889634f
#define LN2   0.6931471805599453f
__device__ __forceinline__ float siluf(float x){ return x * frcp(1.f + fex2(-x * LOG2E)); }
__device__ __forceinline__ float softplusf(float x){
    return (x > 20.f) ? x : LN2 * flg2(1.f + fex2(x * LOG2E));
}
__device__ __forceinline__ uint32_t f2tf32(float f){
    uint32_t u; asm("cvt.rna.tf32.f32 %0, %1;" : "=r"(u) : "f"(f)); return u;
}

__device__ __forceinline__ float blockReduce256(float v, float* red) {
    int lane = threadIdx.x & 31, w = threadIdx.x >> 5;
    #pragma unroll
    for (int o = 16; o; o >>= 1) v += __shfl_xor_sync(0xffffffffu, v, o);
    __syncthreads();
    if (lane == 0) red[w] = v;
    __syncthreads();
    float t = 0.f;
    if (w == 0) {
        t = (lane < 8) ? red[lane] : 0.f;
        #pragma unroll
        for (int o = 4; o; o >>= 1) t += __shfl_xor_sync(0xffffffffu, t, o);
        if (lane == 0) red[0] = t;
    }
    __syncthreads();
    float r = red[0];
    __syncthreads();
    return r;
}

// ---------------- tf32 tensor-core GEMM ---------------------------------------
__device__ __forceinline__ void mma_tf32(float c[4], uint32_t a0, uint32_t a1, uint32_t a2, uint32_t a3,
                                         uint32_t b0, uint32_t b1) {
    asm volatile(
        "mma.sync.aligned.m16n8k8.row.col.f32.tf32.tf32.f32 "
        "{%0,%1,%2,%3},{%4,%5,%6,%7},{%8,%9},{%0,%1,%2,%3};\n"
        : "+f"(c[0]), "+f"(c[1]), "+f"(c[2]), "+f"(c[3])
        : "r"(a0), "r"(a1), "r"(a2), "r"(a3), "r"(b0), "r"(b1));
}

template<int BM, int BN, int WM, int WN>
__global__ void __launch_bounds__((BM/WM)*(BN/WN)*32)
mmatf32(const float* __restrict__ A, const float* __restrict__ B,
        float* __restrict__ C, int M, int N, int K)
{
    constexpr int BK = 32;
    constexpr int WARPS_M = BM / WM, WARPS_N = BN / WN;
    constexpr int NTHR = WARPS_M * WARPS_N * 32;
    constexpr int MI = WM / 16, NI = WN / 8;
    constexpr int A_C4 = NTHR / BM;
    constexpr int A_IT = BM * (BK/4) / NTHR;
    constexpr int B_R  = NTHR / (BN / 4);
    constexpr int B_IT = (BK) * (BN/4) / NTHR;

    extern __shared__ float sm[];
    float* As = sm;
    float* Bs = sm + 2 * BK * BM;

    const int tid = threadIdx.x;
    const int lane = tid & 31, warp = tid >> 5;
    const int g = lane >> 2, tin = lane & 3;
    const int wm = warp % WARPS_M, wn = warp / WARPS_M;
    const int m_base = wm * WM, n_base = wn * WN;
    const int m0 = blockIdx.y * BM, n0 = blockIdx.x * BN;

    const int mA = tid % BM, c4A = tid / BM;
    const int n4B = tid % (BN / 4), kB = tid / (BN / 4);
    const int gmA = m0 + mA;
    const bool aval = (gmA < M);

    float acc[MI][NI][4];
    #pragma unroll
    for (int i = 0; i < MI; i++)
        #pragma unroll
        for (int j = 0; j < NI; j++)
            #pragma unroll
            for (int t = 0; t < 4; t++) acc[i][j][t] = 0.f;

    float4 av[A_IT], bv[B_IT];

    auto ldgA = [&](int k0) {
        #pragma unroll
        for (int i = 0; i < A_IT; i++) {
            int k4 = c4A + i * A_C4;
            av[i] = aval ? *(const float4*)(A + (size_t)gmA * K + k0 + k4 * 4)
                         : make_float4(0.f,0.f,0.f,0.f);
        }
    };
    auto ldgB = [&](int k0) {
        #pragma unroll
        for (int i = 0; i < B_IT; i++) {
            int k = kB + i * B_R;
            int gn = n0 + n4B * 4;
            const float* br = B + (size_t)(k0 + k) * N;
            float4 v;
            if (gn + 3 < N) v = *(const float4*)(br + gn);
            else {
                v.x = (gn   < N) ? br[gn]   : 0.f;
                v.y = (gn+1 < N) ? br[gn+1] : 0.f;
                v.z = (gn+2 < N) ? br[gn+2] : 0.f;
                v.w = (gn+3 < N) ? br[gn+3] : 0.f;
            }
            bv[i] = v;
        }
    };
    auto stsA = [&](int buf) {
        float* dst = As + buf * BK * BM;
        #pragma unroll
        for (int i = 0; i < A_IT; i++) {
            int k4 = c4A + i * A_C4;
            float vv[4] = {av[i].x, av[i].y, av[i].z, av[i].w};
            #pragma unroll
            for (int j = 0; j < 4; j++) {
                int k = k4 * 4 + j;
                dst[k * BM + (mA ^ ((k & 3) * 8))] = __uint_as_float(f2tf32(vv[j]));
            }
        }
    };
    auto stsB = [&](int buf) {
        float* dst = Bs + buf * BK * BN;
        #pragma unroll
        for (int i = 0; i < B_IT; i++) {
            int k = kB + i * B_R;
            int n = n4B * 4;
            float4 v = bv[i];
            v.x = __uint_as_float(f2tf32(v.x));
            v.y = __uint_as_float(f2tf32(v.y));
            v.z = __uint_as_float(f2tf32(v.z));
            v.w = __uint_as_float(f2tf32(v.w));
            *(float4*)(dst + k * BN + (n ^ ((k & 3) * 8))) = v;
        }
    };
    auto compute = [&](int buf) {
        const float* as = As + buf * BK * BM;
        const float* bs = Bs + buf * BK * BN;
        const int s = tin * 8;
        #pragma unroll
        for (int ks = 0; ks < 4; ks++) {
            int ka = ks * 8 + tin;
            uint32_t af[MI][4], bf[NI][2];
            #pragma unroll
            for (int mi = 0; mi < MI; mi++) {
                int r0 = m_base + mi * 16 + g;
                af[mi][0] = __float_as_uint(as[ka * BM + (r0 ^ s)]);
                af[mi][1] = __float_as_uint(as[ka * BM + ((r0 + 8) ^ s)]);
                af[mi][2] = __float_as_uint(as[(ka + 4) * BM + (r0 ^ s)]);
                af[mi][3] = __float_as_uint(as[(ka + 4) * BM + ((r0 + 8) ^ s)]);
            }
            #pragma unroll
            for (int ni = 0; ni < NI; ni++) {
                int c0 = n_base + ni * 8 + g;
                bf[ni][0] = __float_as_uint(bs[ka * BN + (c0 ^ s)]);
                bf[ni][1] = __float_as_uint(bs[(ka + 4) * BN + (c0 ^ s)]);
            }
            #pragma unroll
            for (int mi = 0; mi < MI; mi++)
                #pragma unroll
                for (int ni = 0; ni < NI; ni++)
                    mma_tf32(acc[mi][ni], af[mi][0], af[mi][1], af[mi][2], af[mi][3],
                             bf[ni][0], bf[ni][1]);
        }
    };

    int nchunk = K / BK;
    ldgA(0); ldgB(0);
    stsA(0); stsB(0);
    __syncthreads();
    int buf = 0;
    for (int kc = 1; kc < nchunk; kc++) {
        ldgA(kc * BK); ldgB(kc * BK);
        compute(buf);
        stsA(buf ^ 1); stsB(buf ^ 1);
        __syncthreads();
        buf ^= 1;
    }
    compute(buf);

    #pragma unroll
    for (int mi = 0; mi < MI; mi++) {
        int gr0 = m0 + m_base + mi * 16 + g;
        int gr1 = gr0 + 8;
        #pragma unroll
        for (int ni = 0; ni < NI; ni++) {
            int gc = n0 + n_base + ni * 8 + tin * 2;
            if (gc < N) {
                if (gr0 < M) *(float2*)(C + (size_t)gr0 * N + gc) = make_float2(acc[mi][ni][0], acc[mi][ni][1]);
                if (gr1 < M) *(float2*)(C + (size_t)gr1 * N + gc) = make_float2(acc[mi][ni][2], acc[mi][ni][3]);
            }
        }
    }
}

// ---------------- patchify + LN1 ----------------------------------------------
__global__ void patchify_ln(const float* __restrict__ img,
                            const float* __restrict__ gg, const float* __restrict__ bb)
{
    __shared__ float sv[PD];
    __shared__ float red[8];
    int r = blockIdx.x;
    int b = r / NPATCH, p = r % NPATCH;
    int hh = p / 14, ww = p % 14;
    int tid = threadIdx.x;
    float lsum = 0.f;
    #pragma unroll
    for (int e = tid; e < PD; e += 256) {
        int c = e % 3, t = e / 3, p2 = t % 16, p1 = t / 16;
        float v = img[(((size_t)(b * 3 + c) * 224 + hh * 16 + p1) * 224) + ww * 16 + p2];
        sv[e] = v; lsum += v;
    }
    float mu = blockReduce256(lsum, red) * (1.f / PD);
    float lq = 0.f;
    #pragma unroll
    for (int e = tid; e < PD; e += 256) { float d = sv[e] - mu; lq += d * d; }
    float var = blockReduce256(lq, red) * (1.f / PD);
    float rs = rsqrtf(var + 1e-5f);
    #pragma unroll
    for (int e = tid; e < PD; e += 256)
        g_xp[(size_t)r * PD + e] = (sv[e] - mu) * rs * gg[e] + bb[e];
}

// ---------------- bias + LN2 + pos_emb + cls token -----------------------------
__global__ void pe2_posemb(const float* __restrict__ pe_b,
                           const float* __restrict__ g2, const float* __restrict__ b2,
                           const float* __restrict__ pos, const float* __restrict__ cls)
{
    __shared__ float red[8];
    int blk = blockIdx.x;
    int c = threadIdx.x;
    if (blk < PROWS) {
        int b = blk / NPATCH, p = blk % NPATCH;
        float v = g_xe[(size_t)blk * DIMM + c] + pe_b[c];
        float mu = blockReduce256(v, red) * (1.f / DIMM);
        float d = v - mu;
        float var = blockReduce256(d * d, red) * (1.f / DIMM);
        float o = d * rsqrtf(var + 1e-5f) * g2[c] + b2[c];
        g_x[((size_t)(b * SEQ + 1 + p)) * DIMM + c] = o + pos[(1 + p) * DIMM + c];
    } else {
        int b = blk - PROWS;
        g_x[((size_t)(b * SEQ)) * DIMM + c] = cls[c] + pos[c];
    }
}

// ---------------- residual update + LN (warp per row, float4) -----------------
__global__ void ln_res(const float* __restrict__ lw, const float* __restrict__ lb, int init)
{
    int row = blockIdx.x * 8 + (threadIdx.x >> 5);
    int lane = threadIdx.x & 31;
    const float4* xr = (const float4*)(g_x + (size_t)row * DIMM);
    float4* rr = (float4*)(g_res + (size_t)row * DIMM);
    float4 v[2]; float s = 0.f;
    #pragma unroll
    for (int j = 0; j < 2; j++) {
        float4 t = xr[lane + j * 32];
        if (!init) {
            float4 r = rr[lane + j * 32];
            t.x += r.x; t.y += r.y; t.z += r.z; t.w += r.w;
        }
        rr[lane + j * 32] = t; v[j] = t;
        s += t.x + t.y + t.z + t.w;
    }
    #pragma unroll
    for (int o = 16; o; o >>= 1) s += __shfl_xor_sync(0xffffffffu, s, o);
    float mu = s * (1.f / DIMM);
    float q = 0.f;
    #pragma unroll
    for (int j = 0; j < 2; j++) {
        float4 t = v[j];
        q += (t.x-mu)*(t.x-mu) + (t.y-mu)*(t.y-mu) + (t.z-mu)*(t.z-mu) + (t.w-mu)*(t.w-mu);
    }
    #pragma unroll
    for (int o = 16; o; o >>= 1) q += __shfl_xor_sync(0xffffffffu, q, o);
    float rs = rsqrtf(q * (1.f / DIMM) + 1e-5f);
    const float4* lw4 = (const float4*)lw;
    const float4* lb4 = (const float4*)lb;
    float4* xo = (float4*)(g_xn + (size_t)row * DIMM);
    #pragma unroll
    for (int j = 0; j < 2; j++) {
        float4 t = v[j], w4 = lw4[lane + j*32], b4 = lb4[lane + j*32], o4;
        o4.x = (t.x - mu) * rs * w4.x + b4.x;
        o4.y = (t.y - mu) * rs * w4.y + b4.y;
        o4.z = (t.z - mu) * rs * w4.z + b4.z;
        o4.w = (t.w - mu) * rs * w4.w + b4.w;
        xo[lane + j * 32] = o4;
    }
}

// ---------------- depthwise causal conv (k=4) + silu, float4 over d ------------
__global__ void conv_silu(const float* __restrict__ cw, const float* __restrict__ cb)
{
    int i = blockIdx.x * 256 + threadIdx.x;          // one per 4 channels
    if (i >= NROWS * DI / 4) return;
    int d4 = (i % (DI/4)) * 4;
    int row = i / (DI/4);
    int l = row % SEQ; int b = row / SEQ;
    float4 acc = *(const float4*)(cb + d4);
    #pragma unroll
    for (int k = 0; k < 4; k++) {
        int ll = l - 3 + k;
        if (ll >= 0) {
            float4 x4 = *(const float4*)(g_xz + ((size_t)(b * SEQ + ll)) * (2*DI) + d4);
            acc.x += x4.x * cw[(d4+0)*4 + k];
            acc.y += x4.y * cw[(d4+1)*4 + k];
            acc.z += x4.z * cw[(d4+2)*4 + k];
            acc.w += x4.w * cw[(d4+3)*4 + k];
        }
    }
    acc.x = siluf(acc.x); acc.y = siluf(acc.y); acc.z = siluf(acc.z); acc.w = siluf(acc.w);
    *(float4*)(g_u + (size_t)row * DI + d4) = acc;
}

// ---------------- selective scan: fused dtproj + softplus + scan + epilogue -----
// grid: 16 b * 8 chunks; block 128; 2 threads per channel (8 states each).
// Software pipelined in groups of 4 steps, double-buffered SMEM for dbc rows.
__global__ void scan_k(const float* __restrict__ A_log, const float* __restrict__ Dpv,
                       const float* __restrict__ dtw, const float* __restrict__ dtb)
{
    __shared__ float sdbc[2][4][48];
    int b = blockIdx.x >> 3;
    int chunk = blockIdx.x & 7;
    int tid = threadIdx.x;
    int d = chunk * 64 + (tid >> 1);
    int half = tid & 1;
    int n0 = half * 8;
    int row0 = b * SEQ;

    float A2[8], hst[8];
    #pragma unroll
    for (int j = 0; j < 8; j++) {
        A2[j] = -expf(A_log[(size_t)d * DS + n0 + j]) * LOG2E;
        hst[j] = 0.f;
    }
    float w16[16];
    #pragma unroll
    for (int k = 0; k < 16; k++) w16[k] = dtw[k * DI + d];
    float bias = dtb[d];
    float dpd = Dpv[d];

    auto stage = [&](int grp, int buf) {
        if (tid < 96) {
            int r = tid / 24, off = tid % 24;
            int l = grp * 4 + r;
            float2 v = make_float2(0.f, 0.f);
            if (l < SEQ) v = *(const float2*)(g_dbc + (size_t)(row0 + l) * 48 + off * 2);
            *(float2*)(&sdbc[buf][r][off * 2]) = v;
        }
    };
    float u[4], z[4], un[4], zn[4];
    auto ldreg = [&](int grp, float* uu, float* zz) {
        #pragma unroll
        for (int g2 = 0; g2 < 4; g2++) {
            int l = grp * 4 + g2;
            if (l < SEQ) {
                uu[g2] = g_u [(size_t)(row0 + l) * DI + d];
                zz[g2] = g_xz[(size_t)(row0 + l) * (2*DI) + DI + d];
            } else { uu[g2] = 0.f; zz[g2] = 0.f; }
        }
    };

    stage(0, 0);
    ldreg(0, u, z);
    __syncthreads();

    const int NG = (SEQ + 3) / 4;
    for (int grp = 0; grp < NG; grp++) {
        int buf = grp & 1;
        if (grp + 1 < NG) { stage(grp + 1, buf ^ 1); ldreg(grp + 1, un, zn); }
        #pragma unroll
        for (int g2 = 0; g2 < 4; g2++) {
            int l = grp * 4 + g2;
            if (l < SEQ) {
                float acc = bias;
                #pragma unroll
                for (int k = 0; k < 16; k++) acc += sdbc[buf][g2][k] * w16[k];
                float dt = softplusf(acc);
                float xt = dt * u[g2];
                float y = 0.f;
                #pragma unroll
                for (int j = 0; j < 8; j++) {
                    float dA = fex2(dt * A2[j]);
                    float hv = dA * hst[j] + xt * sdbc[buf][g2][16 + n0 + j];
                    hst[j] = hv;
                    y += hv * sdbc[buf][g2][32 + n0 + j];
                }
                y += __shfl_xor_sync(0xffffffffu, y, 1);
                if (!half)
                    g_y[(size_t)(row0 + l) * DI + d] = (y + u[g2] * dpd) * siluf(z[g2]);
            }
        }
        __syncthreads();
        #pragma unroll
        for (int g2 = 0; g2 < 4; g2++) { u[g2] = un[g2]; z[g2] = zn[g2]; }
    }
}

// ---------------- final LN on token 0 ------------------------------------------
__global__ void ln_cls_k(const float* __restrict__ gw, const float* __restrict__ gb)
{
    __shared__ float red[8];
    int b = blockIdx.x; int c = threadIdx.x;
    size_t idx = (size_t)(b * SEQ) * DIMM + c;
    float v = g_x[idx] + g_res[idx];
    float mu = blockReduce256(v, red) * (1.f / DIMM);
    float d = v - mu;
    float var = blockReduce256(d * d, red) * (1.f / DIMM);
    g_cls[b * DIMM + c] = d * rsqrtf(var + 1e-5f) * gw[c] + gb[c];
}

// ---------------- head ----------------------------------------------------------
__global__ void head_k(const float* __restrict__ hw, const float* __restrict__ hb,
                       float* __restrict__ out)
{
    int i = blockIdx.x * 256 + threadIdx.x;
    if (i >= BB * NCLS) return;
    int n = i % NCLS, b = i / NCLS;
    const float* xr = g_cls + b * DIMM;
    float acc = hb[n];
    #pragma unroll 4
    for (int k = 0; k < DIMM; k++) acc += xr[k] * hw[k * NCLS + n];
    out[i] = acc;
}

// ---------------- launch ---------------------------------------------------------
extern "C" void kernel_launch(void* const* d_in, const int* in_sizes, int n_in,
                              void* d_out, int out_size)
{
    (void)in_sizes; (void)n_in; (void)out_size;
    const float* img      = (const float*)d_in[0];
    const float* pe_ln1_g = (const float*)d_in[1];
    const float* pe_ln1_b = (const float*)d_in[2];
    const float* pe_w     = (const float*)d_in[3];
    const float* pe_b     = (const float*)d_in[4];
    const float* pe_ln2_g = (const float*)d_in[5];
    const float* pe_ln2_b = (const float*)d_in[6];
    const float* pos_emb  = (const float*)d_in[7];
    const float* cls_tok  = (const float*)d_in[8];
    const float* ln_w     = (const float*)d_in[9];
    const float* ln_b     = (const float*)d_in[10];
    const float* in_w     = (const float*)d_in[11];
    const float* conv_w   = (const float*)d_in[12];
    const float* conv_b   = (const float*)d_in[13];
    const float* xproj_w  = (const float*)d_in[14];
    const float* dtproj_w = (const float*)d_in[15];
    const float* dtproj_b = (const float*)d_in[16];
    const float* A_log    = (const float*)d_in[17];
    const float* Dp       = (const float*)d_in[18];
    const float* out_w    = (const float*)d_in[19];
    const float* normf_w  = (const float*)d_in[20];
    const float* normf_b  = (const float*)d_in[21];
    const float* head_w   = (const float*)d_in[22];
    const float* head_b   = (const float*)d_in[23];
    float* out = (float*)d_out;

    float *p_xp, *p_xe, *p_xn, *p_xz, *p_y, *p_x, *p_u, *p_dbc;
    cudaGetSymbolAddress((void**)&p_xp, g_xp);
    cudaGetSymbolAddress((void**)&p_xe, g_xe);
    cudaGetSymbolAddress((void**)&p_xn, g_xn);
    cudaGetSymbolAddress((void**)&p_xz, g_xz);
    cudaGetSymbolAddress((void**)&p_y , g_y );
    cudaGetSymbolAddress((void**)&p_x , g_x );
    cudaGetSymbolAddress((void**)&p_u , g_u );
    cudaGetSymbolAddress((void**)&p_dbc, g_dbc);

    const int SMEM1 = 2 * 32 * (128 + 128) * 4;   // 65536
    const int SMEM2 = 2 * 32 * (64 + 64) * 4;     // 32768
    cudaFuncSetAttribute((const void*)mmatf32<128,128,64,32>,
                         cudaFuncAttributeMaxDynamicSharedMemorySize, SMEM1);
    cudaFuncSetAttribute((const void*)mmatf32<64,64,32,32>,
                         cudaFuncAttributeMaxDynamicSharedMemorySize, SMEM2);

    // patch embed
    patchify_ln<<<PROWS, 256>>>(img, pe_ln1_g, pe_ln1_b);
    {
        dim3 grid(DIMM / 64, PROWS / 64);
        mmatf32<64,64,32,32><<<grid, 128, SMEM2>>>(p_xp, pe_w, p_xe, PROWS, DIMM, PD);
    }
    pe2_posemb<<<PROWS + BB, 256>>>(pe_b, pe_ln2_g, pe_ln2_b, pos_emb, cls_tok);

    for (int i = 0; i < 8; i++) {
        ln_res<<<NROWS / 8, 256>>>(ln_w + i * DIMM, ln_b + i * DIMM, (i == 0) ? 1 : 0);
        {   // g_xz = g_xn @ in_w[i]  (3152 x 1024 x 256)
            dim3 grid((2 * DI) / 128, (NROWS + 127) / 128);
            mmatf32<128,128,64,32><<<grid, 256, SMEM1>>>(p_xn, in_w + (size_t)i * DIMM * 2 * DI,
                                                         p_xz, NROWS, 2 * DI, DIMM);
        }
        conv_silu<<<(NROWS * DI / 4 + 255) / 256, 256>>>(conv_w + (size_t)i * DI * 4, conv_b + i * DI);
        {   // g_dbc = g_u @ xproj_w[i]  (3152 x 48 x 512)
            dim3 grid(1, (NROWS + 63) / 64);
            mmatf32<64,64,32,32><<<grid, 128, SMEM2>>>(p_u, xproj_w + (size_t)i * DI * 48,
                                                       p_dbc, NROWS, 48, DI);
        }
        scan_k<<<BB * 8, 128>>>(A_log + (size_t)i * DI * DS, Dp + i * DI,
                                dtproj_w + (size_t)i * 16 * DI, dtproj_b + i * DI);
        {   // g_x = g_y @ out_w[i]  (3152 x 256 x 512)
            dim3 grid(DIMM / 64, (NROWS + 63) / 64);
            mmatf32<64,64,32,32><<<grid, 128, SMEM2>>>(p_y, out_w + (size_t)i * DI * DIMM,
                                                       p_x, NROWS, DIMM, DI);
        }
    }

    ln_cls_k<<<BB, 256>>>(normf_w, normf_b);
    head_k<<<(BB * NCLS + 255) / 256, 256>>>(head_w, head_b, out);
}

// round 4
// speedup vs baseline: 3.5278x; 1.6853x over previous
#include <cuda_runtime.h>
#include <cuda_bf16.h>
#include <math.h>
#include <stdint.h>

#define BB 16
#define SEQ 197
#define NROWS (BB*SEQ)        // 3152
#define DIMM 256
#define DI 512
#define DS 16
#define PD 768
#define NPATCH 196
#define PROWS (BB*NPATCH)     // 3136
#define NCLS 1000
#define NL 8

// ---------------- scratch (device globals; no allocation allowed) -------------
__device__ __align__(256) __nv_bfloat16 g_xpb[PROWS*PD];     // patch rows (bf16, GEMM A)
__device__ __align__(256) float g_xe [PROWS*DIMM];
__device__ __align__(256) float g_x  [NROWS*DIMM];
__device__ __align__(256) float g_res[NROWS*DIMM];
__device__ __align__(256) __nv_bfloat16 g_xnb[NROWS*DIMM];   // LN out (bf16, GEMM A)
__device__ __align__(256) float g_xz [NROWS*2*DI];
__device__ __align__(256) __nv_bfloat16 g_ub [NROWS*DI];     // conv out bf16 (GEMM A)
__device__ __align__(256) float g_uf [NROWS*DI];             // conv out fp32 (scan)
__device__ __align__(256) float g_dbc[NROWS*48];
__device__ __align__(256) __nv_bfloat16 g_yb [NROWS*DI];     // scan out bf16 (GEMM A)
__device__ __align__(256) float g_cls[BB*DIMM];

// bf16 weights (converted per launch)
__device__ __align__(256) __nv_bfloat16 w_pe [PD*DIMM];
__device__ __align__(256) __nv_bfloat16 w_in [NL*DIMM*2*DI];
__device__ __align__(256) __nv_bfloat16 w_xp [NL*DI*48];
__device__ __align__(256) __nv_bfloat16 w_out[NL*DI*DIMM];

// ---------------- fast math helpers -------------------------------------------
__device__ __forceinline__ float fex2(float x){ float y; asm("ex2.approx.ftz.f32 %0,%1;":"=f"(y):"f"(x)); return y; }
__device__ __forceinline__ float flg2(float x){ float y; asm("lg2.approx.ftz.f32 %0,%1;":"=f"(y):"f"(x)); return y; }
__device__ __forceinline__ float frcp(float x){ float y; asm("rcp.approx.ftz.f32 %0,%1;":"=f"(y):"f"(x)); return y; }
#define LOG2E 1.4426950408889634f
#define LN2   0.6931471805599453f
__device__ __forceinline__ float siluf(float x){ return x * frcp(1.f + fex2(-x * LOG2E)); }
__device__ __forceinline__ float softplusf(float x){
    return (x > 20.f) ? x : LN2 * flg2(1.f + fex2(x * LOG2E));
}

__device__ __forceinline__ float blockReduce256(float v, float* red) {
    int lane = threadIdx.x & 31, w = threadIdx.x >> 5;
    #pragma unroll
    for (int o = 16; o; o >>= 1) v += __shfl_xor_sync(0xffffffffu, v, o);
    __syncthreads();
    if (lane == 0) red[w] = v;
    __syncthreads();
    float t = 0.f;
    if (w == 0) {
        t = (lane < 8) ? red[lane] : 0.f;
        #pragma unroll
        for (int o = 4; o; o >>= 1) t += __shfl_xor_sync(0xffffffffu, t, o);
        if (lane == 0) red[0] = t;
    }
    __syncthreads();
    float r = red[0];
    __syncthreads();
    return r;
}

// ---------------- weight convert -----------------------------------------------
__global__ void cvt_bf16(const float* __restrict__ in, __nv_bfloat16* __restrict__ out, int n4)
{
    int i = blockIdx.x * 256 + threadIdx.x;
    if (i >= n4) return;
    float4 v = ((const float4*)in)[i];
    __nv_bfloat162 lo = __floats2bfloat162_rn(v.x, v.y);
    __nv_bfloat162 hi = __floats2bfloat162_rn(v.z, v.w);
    ((__nv_bfloat162*)out)[2*i]   = lo;
    ((__nv_bfloat162*)out)[2*i+1] = hi;
}

// ---------------- bf16 tensor-core GEMM (cp.async + ldmatrix + m16n8k16) -------
__device__ __forceinline__ void ldsm_x4(uint32_t a[4], uint32_t addr){
    asm volatile("ldmatrix.sync.aligned.m8n8.x4.shared.b16 {%0,%1,%2,%3}, [%4];"
        : "=r"(a[0]),"=r"(a[1]),"=r"(a[2]),"=r"(a[3]) : "r"(addr));
}
__device__ __forceinline__ void ldsm_x2t(uint32_t b[2], uint32_t addr){
    asm volatile("ldmatrix.sync.aligned.m8n8.x2.trans.shared.b16 {%0,%1}, [%2];"
        : "=r"(b[0]),"=r"(b[1]) : "r"(addr));
}
__device__ __forceinline__ void mma_bf16(float c[4], const uint32_t a[4], const uint32_t b[2]){
    asm volatile(
        "mma.sync.aligned.m16n8k16.row.col.f32.bf16.bf16.f32 "
        "{%0,%1,%2,%3},{%4,%5,%6,%7},{%8,%9},{%0,%1,%2,%3};\n"
        : "+f"(c[0]), "+f"(c[1]), "+f"(c[2]), "+f"(c[3])
        : "r"(a[0]), "r"(a[1]), "r"(a[2]), "r"(a[3]), "r"(b[0]), "r"(b[1]));
}
__device__ __forceinline__ void cp16(uint32_t dst, const void* src, int srcbytes){
    asm volatile("cp.async.cg.shared.global [%0], [%1], 16, %2;\n"
        :: "r"(dst), "l"(src), "r"(srcbytes));
}

template<int BM, int BN, int WM, int WN>
__global__ void __launch_bounds__((BM/WM)*(BN/WN)*32)
mmabf16(const __nv_bfloat16* __restrict__ A, const __nv_bfloat16* __restrict__ B,
        float* __restrict__ C, int M, int N, int K)
{
    constexpr int BK = 64;
    constexpr int WARPS_M = BM/WM, WARPS_N = BN/WN;
    constexpr int NTHR = WARPS_M*WARPS_N*32;
    constexpr int MI = WM/16, NI = WN/8;
    constexpr int ABYTES = BM*128;          // BM rows x 64 bf16
    constexpr int BBYTES = 64*BN*2;         // 64 k-rows x BN bf16
    constexpr int BUF = ABYTES + BBYTES;
    constexpr int A_OPS = BM*8/NTHR;
    constexpr int BN8 = BN/8;
    constexpr int B_OPS = 64*BN8/NTHR;

    extern __shared__ char smc[];
    uint32_t smBase;
    asm("{.reg .u64 t; cvta.to.shared.u64 t, %1; cvt.u32.u64 %0, t;}" : "=r"(smBase) : "l"(smc));

    const int tid = threadIdx.x;
    const int lane = tid & 31, warp = tid >> 5;
    const int g = lane >> 2, tin = lane & 3;
    const int wm = warp % WARPS_M, wn = warp / WARPS_M;
    const int m_base = wm*WM, n_base = wn*WN;
    const int m0 = blockIdx.y * BM, n0 = blockIdx.x * BN;

    float acc[MI][NI][4];
    #pragma unroll
    for (int i = 0; i < MI; i++)
        #pragma unroll
        for (int j = 0; j < NI; j++)
            #pragma unroll
            for (int t = 0; t < 4; t++) acc[i][j][t] = 0.f;

    auto stage = [&](int kc, int buf) {
        // A tile: BM x 64 bf16
        #pragma unroll
        for (int i = 0; i < A_OPS; i++) {
            int idx = tid + i*NTHR;
            int m = idx >> 3, c = idx & 7;
            int gm = m0 + m;
            int sz = (gm < M) ? 16 : 0;
            int gmc = (gm < M) ? gm : (M-1);
            uint32_t dst = smBase + buf*BUF + m*128 + ((c ^ (m & 7)) << 4);
            cp16(dst, A + (size_t)gmc*K + kc*64 + c*8, sz);
        }
        // B tile: 64 x BN bf16
        #pragma unroll
        for (int i = 0; i < B_OPS; i++) {
            int idx = tid + i*NTHR;
            int nc = idx % BN8, k = idx / BN8;
            int gn = n0 + nc*8;
            int sz = (gn < N) ? 16 : 0;
            int gnc = (gn < N) ? gn : 0;
            uint32_t dst = smBase + buf*BUF + ABYTES + k*(BN*2) + ((nc ^ (k & 7)) << 4);
            cp16(dst, B + (size_t)(kc*64 + k)*N + gnc, sz);
        }
        asm volatile("cp.async.commit_group;\n");
    };

    auto compute = [&](int buf) {
        const uint32_t aBuf = smBase + buf*BUF;
        const uint32_t bBuf = aBuf + ABYTES;
        const int sub = lane >> 3, r = lane & 7;
        const int mloc = m_base + (sub & 1)*8 + r;       // row for A ldmatrix
        const int khalf = sub >> 1;                       // which k-chunk half
        const int msw = mloc & 7;
        const int kloc = lane & 15;                       // B ldmatrix k within step
        const int nb = n_base >> 3;
        #pragma unroll
        for (int ks = 0; ks < 4; ks++) {
            uint32_t af[MI][4], bf[NI][2];
            #pragma unroll
            for (int mi = 0; mi < MI; mi++) {
                uint32_t addr = aBuf + (mloc + mi*16)*128 + (((ks*2 + khalf) ^ msw) << 4);
                ldsm_x4(af[mi], addr);
            }
            #pragma unroll
            for (int ni = 0; ni < NI; ni++) {
                int k = ks*16 + kloc;
                uint32_t addr = bBuf + k*(BN*2) + (((nb + ni) ^ (kloc & 7)) << 4);
                ldsm_x2t(bf[ni], addr);
            }
            #pragma unroll
            for (int mi = 0; mi < MI; mi++)
                #pragma unroll
                for (int ni = 0; ni < NI; ni++)
                    mma_bf16(acc[mi][ni], af[mi], bf[ni]);
        }
    };

    const int ntile = K / 64;
    stage(0, 0);
    if (ntile > 1) stage(1, 1);
    for (int kc = 0; kc < ntile; kc++) {
        if (kc + 1 < ntile) asm volatile("cp.async.wait_group 1;\n");
        else                asm volatile("cp.async.wait_group 0;\n");
        __syncthreads();
        compute(kc & 1);
        __syncthreads();
        if (kc + 2 < ntile) stage(kc + 2, kc & 1);
    }

    #pragma unroll
    for (int mi = 0; mi < MI; mi++) {
        int gr0 = m0 + m_base + mi*16 + g;
        int gr1 = gr0 + 8;
        #pragma unroll
        for (int ni = 0; ni < NI; ni++) {
            int gc = n0 + n_base + ni*8 + tin*2;
            if (gc < N) {
                if (gr0 < M) *(float2*)(C + (size_t)gr0*N + gc) = make_float2(acc[mi][ni][0], acc[mi][ni][1]);
                if (gr1 < M) *(float2*)(C + (size_t)gr1*N + gc) = make_float2(acc[mi][ni][2], acc[mi][ni][3]);
            }
        }
    }
}

// ---------------- patchify + LN1 (writes bf16) ----------------------------------
__global__ void patchify_ln(const float* __restrict__ img,
                            const float* __restrict__ gg, const float* __restrict__ bb)
{
    __shared__ float sv[PD];
    __shared__ float red[8];
    int r = blockIdx.x;
    int b = r / NPATCH, p = r % NPATCH;
    int hh = p / 14, ww = p % 14;
    int tid = threadIdx.x;
    float lsum = 0.f;
    #pragma unroll
    for (int e = tid; e < PD; e += 256) {
        int c = e % 3, t = e / 3, p2 = t % 16, p1 = t / 16;
        float v = img[(((size_t)(b * 3 + c) * 224 + hh * 16 + p1) * 224) + ww * 16 + p2];
        sv[e] = v; lsum += v;
    }
    float mu = blockReduce256(lsum, red) * (1.f / PD);
    float lq = 0.f;
    #pragma unroll
    for (int e = tid; e < PD; e += 256) { float d = sv[e] - mu; lq += d * d; }
    float var = blockReduce256(lq, red) * (1.f / PD);
    float rs = rsqrtf(var + 1e-5f);
    #pragma unroll
    for (int e = tid; e < PD; e += 256)
        g_xpb[(size_t)r * PD + e] = __float2bfloat16((sv[e] - mu) * rs * gg[e] + bb[e]);
}

// ---------------- bias + LN2 + pos_emb + cls token -----------------------------
__global__ void pe2_posemb(const float* __restrict__ pe_b,
                           const float* __restrict__ g2, const float* __restrict__ b2,
                           const float* __restrict__ pos, const float* __restrict__ cls)
{
    __shared__ float red[8];
    int blk = blockIdx.x;
    int c = threadIdx.x;
    if (blk < PROWS) {
        int b = blk / NPATCH, p = blk % NPATCH;
        float v = g_xe[(size_t)blk * DIMM + c] + pe_b[c];
        float mu = blockReduce256(v, red) * (1.f / DIMM);
        float d = v - mu;
        float var = blockReduce256(d * d, red) * (1.f / DIMM);
        float o = d * rsqrtf(var + 1e-5f) * g2[c] + b2[c];
        g_x[((size_t)(b * SEQ + 1 + p)) * DIMM + c] = o + pos[(1 + p) * DIMM + c];
    } else {
        int b = blk - PROWS;
        g_x[((size_t)(b * SEQ)) * DIMM + c] = cls[c] + pos[c];
    }
}

// ---------------- residual + LN (warp/row, float4 in, bf16 out) -----------------
__global__ void ln_res(const float* __restrict__ lw, const float* __restrict__ lb, int init)
{
    int row = blockIdx.x * 8 + (threadIdx.x >> 5);
    int lane = threadIdx.x & 31;
    const float4* xr = (const float4*)(g_x + (size_t)row * DIMM);
    float4* rr = (float4*)(g_res + (size_t)row * DIMM);
    float4 v[2]; float s = 0.f;
    #pragma unroll
    for (int j = 0; j < 2; j++) {
        float4 t = xr[lane + j * 32];
        if (!init) {
            float4 r = rr[lane + j * 32];
            t.x += r.x; t.y += r.y; t.z += r.z; t.w += r.w;
        }
        rr[lane + j * 32] = t; v[j] = t;
        s += t.x + t.y + t.z + t.w;
    }
    #pragma unroll
    for (int o = 16; o; o >>= 1) s += __shfl_xor_sync(0xffffffffu, s, o);
    float mu = s * (1.f / DIMM);
    float q = 0.f;
    #pragma unroll
    for (int j = 0; j < 2; j++) {
        float4 t = v[j];
        q += (t.x-mu)*(t.x-mu) + (t.y-mu)*(t.y-mu) + (t.z-mu)*(t.z-mu) + (t.w-mu)*(t.w-mu);
    }
    #pragma unroll
    for (int o = 16; o; o >>= 1) q += __shfl_xor_sync(0xffffffffu, q, o);
    float rs = rsqrtf(q * (1.f / DIMM) + 1e-5f);
    const float4* lw4 = (const float4*)lw;
    const float4* lb4 = (const float4*)lb;
    __nv_bfloat162* xo = (__nv_bfloat162*)(g_xnb + (size_t)row * DIMM);
    #pragma unroll
    for (int j = 0; j < 2; j++) {
        float4 t = v[j], w4 = lw4[lane + j*32], b4 = lb4[lane + j*32];
        float ox = (t.x - mu) * rs * w4.x + b4.x;
        float oy = (t.y - mu) * rs * w4.y + b4.y;
        float oz = (t.z - mu) * rs * w4.z + b4.z;
        float ow = (t.w - mu) * rs * w4.w + b4.w;
        xo[(lane + j*32)*2]     = __floats2bfloat162_rn(ox, oy);
        xo[(lane + j*32)*2 + 1] = __floats2bfloat162_rn(oz, ow);
    }
}

// ---------------- depthwise causal conv (k=4) + silu ----------------------------
__global__ void conv_silu(const float* __restrict__ cw, const float* __restrict__ cb)
{
    int i = blockIdx.x * 256 + threadIdx.x;
    if (i >= NROWS * DI / 4) return;
    int d4 = (i % (DI/4)) * 4;
    int row = i / (DI/4);
    int l = row % SEQ; int b = row / SEQ;
    float4 acc = *(const float4*)(cb + d4);
    #pragma unroll
    for (int k = 0; k < 4; k++) {
        int ll = l - 3 + k;
        if (ll >= 0) {
            float4 x4 = *(const float4*)(g_xz + ((size_t)(b * SEQ + ll)) * (2*DI) + d4);
            acc.x += x4.x * cw[(d4+0)*4 + k];
            acc.y += x4.y * cw[(d4+1)*4 + k];
            acc.z += x4.z * cw[(d4+2)*4 + k];
            acc.w += x4.w * cw[(d4+3)*4 + k];
        }
    }
    acc.x = siluf(acc.x); acc.y = siluf(acc.y); acc.z = siluf(acc.z); acc.w = siluf(acc.w);
    *(float4*)(g_uf + (size_t)row * DI + d4) = acc;
    __nv_bfloat162* ub = (__nv_bfloat162*)(g_ub + (size_t)row * DI + d4);
    ub[0] = __floats2bfloat162_rn(acc.x, acc.y);
    ub[1] = __floats2bfloat162_rn(acc.z, acc.w);
}

// ---------------- selective scan: fused dtproj + softplus + scan + epilogue -----
__global__ void scan_k(const float* __restrict__ A_log, const float* __restrict__ Dpv,
                       const float* __restrict__ dtw, const float* __restrict__ dtb)
{
    __shared__ float sdbc[2][4][48];
    int b = blockIdx.x >> 3;
    int chunk = blockIdx.x & 7;
    int tid = threadIdx.x;
    int d = chunk * 64 + (tid >> 1);
    int half = tid & 1;
    int n0 = half * 8;
    int row0 = b * SEQ;

    float A2[8], hst[8];
    #pragma unroll
    for (int j = 0; j < 8; j++) {
        A2[j] = -expf(A_log[(size_t)d * DS + n0 + j]) * LOG2E;
        hst[j] = 0.f;
    }
    float w16[16];
    #pragma unroll
    for (int k = 0; k < 16; k++) w16[k] = dtw[k * DI + d];
    float bias = dtb[d];
    float dpd = Dpv[d];

    auto stage = [&](int grp, int buf) {
        if (tid < 96) {
            int r = tid / 24, off = tid % 24;
            int l = grp * 4 + r;
            float2 v = make_float2(0.f, 0.f);
            if (l < SEQ) v = *(const float2*)(g_dbc + (size_t)(row0 + l) * 48 + off * 2);
            *(float2*)(&sdbc[buf][r][off * 2]) = v;
        }
    };
    float u[4], z[4], un[4], zn[4];
    auto ldreg = [&](int grp, float* uu, float* zz) {
        #pragma unroll
        for (int g2 = 0; g2 < 4; g2++) {
            int l = grp * 4 + g2;
            if (l < SEQ) {
                uu[g2] = g_uf[(size_t)(row0 + l) * DI + d];
                zz[g2] = g_xz[(size_t)(row0 + l) * (2*DI) + DI + d];
            } else { uu[g2] = 0.f; zz[g2] = 0.f; }
        }
    };

    stage(0, 0);
    ldreg(0, u, z);
    __syncthreads();

    const int NG = (SEQ + 3) / 4;
    for (int grp = 0; grp < NG; grp++) {
        int buf = grp & 1;
        if (grp + 1 < NG) { stage(grp + 1, buf ^ 1); ldreg(grp + 1, un, zn); }
        #pragma unroll
        for (int g2 = 0; g2 < 4; g2++) {
            int l = grp * 4 + g2;
            if (l < SEQ) {
                float acc = bias;
                #pragma unroll
                for (int k = 0; k < 16; k++) acc += sdbc[buf][g2][k] * w16[k];
                float dt = softplusf(acc);
                float xt = dt * u[g2];
                float y = 0.f;
                #pragma unroll
                for (int j = 0; j < 8; j++) {
                    float dA = fex2(dt * A2[j]);
                    float hv = dA * hst[j] + xt * sdbc[buf][g2][16 + n0 + j];
                    hst[j] = hv;
                    y += hv * sdbc[buf][g2][32 + n0 + j];
                }
                y += __shfl_xor_sync(0xffffffffu, y, 1);
                if (!half)
                    g_yb[(size_t)(row0 + l) * DI + d] =
                        __float2bfloat16((y + u[g2] * dpd) * siluf(z[g2]));
            }
        }
        __syncthreads();
        #pragma unroll
        for (int g2 = 0; g2 < 4; g2++) { u[g2] = un[g2]; z[g2] = zn[g2]; }
    }
}

// ---------------- final LN on token 0 ------------------------------------------
__global__ void ln_cls_k(const float* __restrict__ gw, const float* __restrict__ gb)
{
    __shared__ float red[8];
    int b = blockIdx.x; int c = threadIdx.x;
    size_t idx = (size_t)(b * SEQ) * DIMM + c;
    float v = g_x[idx] + g_res[idx];
    float mu = blockReduce256(v, red) * (1.f / DIMM);
    float d = v - mu;
    float var = blockReduce256(d * d, red) * (1.f / DIMM);
    g_cls[b * DIMM + c] = d * rsqrtf(var + 1e-5f) * gw[c] + gb[c];
}

// ---------------- head ----------------------------------------------------------
__global__ void head_k(const float* __restrict__ hw, const float* __restrict__ hb,
                       float* __restrict__ out)
{
    int i = blockIdx.x * 256 + threadIdx.x;
    if (i >= BB * NCLS) return;
    int n = i % NCLS, b = i / NCLS;
    const float* xr = g_cls + b * DIMM;
    float acc = hb[n];
    #pragma unroll 4
    for (int k = 0; k < DIMM; k++) acc += xr[k] * hw[k * NCLS + n];
    out[i] = acc;
}

// ---------------- launch ---------------------------------------------------------
extern "C" void kernel_launch(void* const* d_in, const int* in_sizes, int n_in,
                              void* d_out, int out_size)
{
    (void)in_sizes; (void)n_in; (void)out_size;
    const float* img      = (const float*)d_in[0];
    const float* pe_ln1_g = (const float*)d_in[1];
    const float* pe_ln1_b = (const float*)d_in[2];
    const float* pe_w     = (const float*)d_in[3];
    const float* pe_b     = (const float*)d_in[4];
    const float* pe_ln2_g = (const float*)d_in[5];
    const float* pe_ln2_b = (const float*)d_in[6];
    const float* pos_emb  = (const float*)d_in[7];
    const float* cls_tok  = (const float*)d_in[8];
    const float* ln_w     = (const float*)d_in[9];
    const float* ln_b     = (const float*)d_in[10];
    const float* in_w     = (const float*)d_in[11];
    const float* conv_w   = (const float*)d_in[12];
    const float* conv_b   = (const float*)d_in[13];
    const float* xproj_w  = (const float*)d_in[14];
    const float* dtproj_w = (const float*)d_in[15];
    const float* dtproj_b = (const float*)d_in[16];
    const float* A_log    = (const float*)d_in[17];
    const float* Dp       = (const float*)d_in[18];
    const float* out_w    = (const float*)d_in[19];
    const float* normf_w  = (const float*)d_in[20];
    const float* normf_b  = (const float*)d_in[21];
    const float* head_w   = (const float*)d_in[22];
    const float* head_b   = (const float*)d_in[23];
    float* out = (float*)d_out;

    __nv_bfloat16 *p_xpb, *p_xnb, *p_ub, *p_yb, *p_wpe, *p_win, *p_wxp, *p_wout;
    float *p_xe, *p_xz, *p_x, *p_dbc;
    cudaGetSymbolAddress((void**)&p_xpb, g_xpb);
    cudaGetSymbolAddress((void**)&p_xnb, g_xnb);
    cudaGetSymbolAddress((void**)&p_ub , g_ub );
    cudaGetSymbolAddress((void**)&p_yb , g_yb );
    cudaGetSymbolAddress((void**)&p_wpe, w_pe );
    cudaGetSymbolAddress((void**)&p_win, w_in );
    cudaGetSymbolAddress((void**)&p_wxp, w_xp );
    cudaGetSymbolAddress((void**)&p_wout, w_out);
    cudaGetSymbolAddress((void**)&p_xe , g_xe );
    cudaGetSymbolAddress((void**)&p_xz , g_xz );
    cudaGetSymbolAddress((void**)&p_x  , g_x  );
    cudaGetSymbolAddress((void**)&p_dbc, g_dbc);

    const int SMEM_BIG   = 2 * (128*128 + 64*128*2);   // 65536
    const int SMEM_SMALL = 2 * (64*128 + 64*64*2);     // 32768
    cudaFuncSetAttribute((const void*)mmabf16<128,128,64,32>,
                         cudaFuncAttributeMaxDynamicSharedMemorySize, SMEM_BIG);
    cudaFuncSetAttribute((const void*)mmabf16<64,64,32,32>,
                         cudaFuncAttributeMaxDynamicSharedMemorySize, SMEM_SMALL);

    // weight conversion (bf16)
    cvt_bf16<<<(PD*DIMM/4 + 255)/256, 256>>>(pe_w, p_wpe, PD*DIMM/4);
    cvt_bf16<<<(NL*DIMM*2*DI/4 + 255)/256, 256>>>(in_w, p_win, NL*DIMM*2*DI/4);
    cvt_bf16<<<(NL*DI*48/4 + 255)/256, 256>>>(xproj_w, p_wxp, NL*DI*48/4);
    cvt_bf16<<<(NL*DI*DIMM/4 + 255)/256, 256>>>(out_w, p_wout, NL*DI*DIMM/4);

    // patch embed
    patchify_ln<<<PROWS, 256>>>(img, pe_ln1_g, pe_ln1_b);
    {   // g_xe = g_xpb @ w_pe  (3136 x 256 x 768)
        dim3 grid(DIMM / 64, PROWS / 64);
        mmabf16<64,64,32,32><<<grid, 128, SMEM_SMALL>>>(p_xpb, p_wpe, p_xe, PROWS, DIMM, PD);
    }
    pe2_posemb<<<PROWS + BB, 256>>>(pe_b, pe_ln2_g, pe_ln2_b, pos_emb, cls_tok);

    for (int i = 0; i < 8; i++) {
        ln_res<<<NROWS / 8, 256>>>(ln_w + i * DIMM, ln_b + i * DIMM, (i == 0) ? 1 : 0);
        {   // g_xz = g_xnb @ w_in[i]  (3152 x 1024 x 256)
            dim3 grid((2 * DI) / 128, (NROWS + 127) / 128);
            mmabf16<128,128,64,32><<<grid, 256, SMEM_BIG>>>(p_xnb, p_win + (size_t)i * DIMM * 2 * DI,
                                                            p_xz, NROWS, 2 * DI, DIMM);
        }
        conv_silu<<<(NROWS * DI / 4 + 255) / 256, 256>>>(conv_w + (size_t)i * DI * 4, conv_b + i * DI);
        {   // g_dbc = g_ub @ w_xp[i]  (3152 x 48 x 512)
            dim3 grid(1, (NROWS + 63) / 64);
            mmabf16<64,64,32,32><<<grid, 128, SMEM_SMALL>>>(p_ub, p_wxp + (size_t)i * DI * 48,
                                                            p_dbc, NROWS, 48, DI);
        }
        scan_k<<<BB * 8, 128>>>(A_log + (size_t)i * DI * DS, Dp + i * DI,
                                dtproj_w + (size_t)i * 16 * DI, dtproj_b + i * DI);
        {   // g_x = g_yb @ w_out[i]  (3152 x 256 x 512)
            dim3 grid(DIMM / 64, (NROWS + 63) / 64);
            mmabf16<64,64,32,32><<<grid, 128, SMEM_SMALL>>>(p_yb, p_wout + (size_t)i * DI * DIMM,
                                                            p_x, NROWS, DIMM, DI);
        }
    }

    ln_cls_k<<<BB, 256>>>(normf_w, normf_b);
    head_k<<<(BB * NCLS + 255) / 256, 256>>>(head_w, head_b, out);
}